// round 17
// baseline (speedup 1.0000x reference)
#include <cuda_runtime.h>
#include <cuda.h>
#include <cstdint>

#define N 2304
#define BB 1024
#define FF 32
#define TEAM 72
#define NCTA (2 * TEAM)
#define NTHR 1024

#define CPS 9                      // chunks per step (256 floats each)
#define CW 256
#define SLOT_FLOATS (32 * CW)      // 8192 floats = 32 KB
#define SLOT_BYTES 32768
#define RING 6
#define DEPTH 5
#define TOTAL (31 * CPS)           // 279 chunks per CTA

// smem float offsets
#define OFF_V    (RING * SLOT_FLOATS)           // 49152
#define OFF_RED  (OFF_V + N)                    // 51456
#define OFF_MBAR (OFF_RED + 1056)               // 52512 (x4 byte-aligned 8)
#define SMEM_BYTES (OFF_MBAR * 4 + 64)          // 210112

// device scratch (no allocation allowed)
__device__ float g_v[FF * N];
__device__ float g_z[FF * N];
__device__ float g_keep[FF * N];
__device__ float g_vsum[TEAM];
__device__ int   g_flagF[FF * TEAM];   // flagF[f*72+k]=1 when fwd CTA k wrote its 32 rows of v_f
__device__ int   g_flagB[FF * TEAM];   // flagB[f*72+k]=1 when bwd CTA k wrote its 32 cols of z_f
__device__ int   g_cntAll;
__device__ __align__(128) CUtensorMap g_tmaps[2];

__global__ void setup_kernel(const int* __restrict__ sel) {
    int tid = threadIdx.x;
    for (int i = tid; i < FF * N; i += NTHR) g_keep[i] = 1.0f;
    for (int i = tid; i < FF * TEAM; i += NTHR) { g_flagF[i] = 0; g_flagB[i] = 0; }
    if (tid == 0) g_cntAll = 0;
    __syncthreads();
    if (tid < 256) {
        int f = sel[3 * tid];
        int node = sel[3 * tid + 1] * 64 + sel[3 * tid + 2];
        g_keep[f * N + node] = 0.0f;
    }
}

__device__ __forceinline__ void mbar_init(uint32_t mb, uint32_t cnt) {
    asm volatile("mbarrier.init.shared.b64 [%0], %1;" :: "r"(mb), "r"(cnt) : "memory");
}
__device__ __forceinline__ void mbar_expect(uint32_t mb, uint32_t bytes) {
    asm volatile("mbarrier.arrive.expect_tx.shared.b64 _, [%0], %1;" :: "r"(mb), "r"(bytes) : "memory");
}
__device__ __forceinline__ void mbar_wait(uint32_t mb, uint32_t ph) {
    asm volatile("{\n\t.reg .pred p;\n\tWL_%=:\n\t"
        "mbarrier.try_wait.parity.acquire.cta.shared::cta.b64 p, [%0], %1, 0x989680;\n\t"
        "@p bra.uni WD_%=;\n\tbra.uni WL_%=;\n\tWD_%=:\n\t}"
        :: "r"(mb), "r"(ph) : "memory");
}
__device__ __forceinline__ void tma3d(uint32_t dst, const CUtensorMap* map,
                                      int x, int y, int z, uint32_t mb) {
    asm volatile("cp.async.bulk.tensor.3d.shared::cta.global.tile.mbarrier::complete_tx::bytes "
        "[%0], [%1, {%2, %3, %4}], [%5];"
        :: "r"(dst), "l"(map), "r"(x), "r"(y), "r"(z), "r"(mb) : "memory");
}

// warp0: wait for the 8 producer flags of one 256-elem segment (lanes 0..7 poll)
__device__ __forceinline__ void waitseg(const int* flags) {
    int l = threadIdx.x & 31;
    bool ok;
    do {
        int x = 1;
        if (l < 8) x = *(volatile const int*)(flags + l);
        ok = __all_sync(0xffffffffu, x != 0);
    } while (!ok);
    __threadfence();   // acquire: order flag observation before data reads
}

// Persistent dataflow solver + fused final. 144 CTAs (1/SM), two teams of 72.
// NO team barrier: per-(step,CTA) flags; each CTA consumes segments in rotated
// order starting at its own, so the straggler tail of step f-1 overlaps step f.
// Weights stream via tensor TMA ring (6 x 32KB, 5 in flight), continuous.
__global__ void __launch_bounds__(NTHR, 1)
solve_kernel(const CUtensorMap* __restrict__ maps,
             const float* __restrict__ B,
             const int* __restrict__ cand, float* __restrict__ out)
{
    extern __shared__ float smem[];
    float* s_slot = smem;
    float* s_v    = smem + OFF_V;
    float* s_red  = smem + OFF_RED;

    uint32_t sbase;
    asm("{ .reg .u64 t; cvta.to.shared.u64 t, %1; cvt.u32.u64 %0, t; }" : "=r"(sbase) : "l"(smem));
    uint32_t mbar = sbase + OFF_MBAR * 4;

    int tid = threadIdx.x;
    int cta = blockIdx.x;
    int warp = tid >> 5, lane = tid & 31;

    if (tid < RING) mbar_init(mbar + tid * 8, 1);
    __syncthreads();

    if (cta < TEAM) {
        // ================= FORWARD TEAM =================
        int r0 = cta * 32;
        int s0 = cta >> 3;                       // own segment: ready earliest
        float myacc = 0.f;
        const CUtensorMap* mapF = &maps[0];
        if (tid == 0) asm volatile("prefetch.tensormap [%0];" :: "l"(mapF));

        // TMA chunk idx -> step idx/9, rotated col block cc
        auto issue = [&](int idx) {
            int slot = idx % RING;
            uint32_t mb = mbar + slot * 8;
            mbar_expect(mb, SLOT_BYTES);
            int ff = idx / CPS, j = idx % CPS;
            int cc = s0 + j; if (cc >= CPS) cc -= CPS;
            uint32_t dst = sbase + (uint32_t)slot * SLOT_BYTES;
            #pragma unroll
            for (int q = 0; q < 4; ++q)
                tma3d(dst + q * 8192u, mapF, cc * CW + q * 64, r0, ff, mb);
        };

        int issued = 0;
        if (tid == 0)
            for (int i = 0; i < DEPTH; ++i) issue(i);
        issued = DEPTH;

        // v0 = keep_0 * b_0 ; publish
        if (tid < 32) {
            int row = r0 + tid;
            float v = g_keep[row] * B[row];
            g_v[row] = v;
            myacc += v;
            __threadfence();
        }
        __syncthreads();
        if (tid == 0) *(volatile int*)&g_flagF[cta] = 1;

        for (int f = 1; f < FF; ++f) {
            float acc = 0.f;
            int g0 = (f - 1) * CPS;
            #pragma unroll
            for (int j = 0; j < CPS; ++j) {
                int idx = g0 + j;
                int cc = s0 + j; if (cc >= CPS) cc -= CPS;
                if (warp == 0) {
                    waitseg(g_flagF + (f - 1) * TEAM + cc * 8);
                    // stage segment cc of v_{f-1} (256 floats, 8 per lane)
                    #pragma unroll
                    for (int t = 0; t < 8; ++t)
                        s_v[cc * CW + lane + t * 32] = g_v[(f - 1) * N + cc * CW + lane + t * 32];
                    if (lane == 0) mbar_wait(mbar + (idx % RING) * 8, (idx / RING) & 1);
                }
                __syncthreads();                 // staged + TMA chunk visible; slot reuse safe
                if (tid == 0 && issued < TOTAL) issue(issued);
                issued++;

                const float* slot = s_slot + (idx % RING) * SLOT_FLOATS;
                const float4* vv  = (const float4*)(s_v + cc * CW);
                #pragma unroll
                for (int jj = 0; jj < 2; ++jj) {
                    int f4 = lane + jj * 32;     // float4 index 0..63 of warp's row
                    int q = f4 >> 4, c4 = f4 & 15;
                    float4 w4 = *(const float4*)(slot + q * 2048 + warp * 64 + c4 * 4);
                    float4 v4 = vv[f4];
                    acc += w4.x * v4.x + w4.y * v4.y + w4.z * v4.z + w4.w * v4.w;
                }
            }
            #pragma unroll
            for (int o = 16; o; o >>= 1)
                acc += __shfl_xor_sync(0xffffffffu, acc, o);
            int ra = r0 + warp;                  // warp owns one row
            if (lane == 0) {
                float va = g_keep[f * N + ra] * (B[f * N + ra] + acc);
                g_v[f * N + ra] = va;
                myacc += va;
                __threadfence();
            }
            __syncthreads();
            if (tid == 0) *(volatile int*)&g_flagF[f * TEAM + cta] = 1;
        }

        #pragma unroll
        for (int o = 16; o; o >>= 1) myacc += __shfl_xor_sync(0xffffffffu, myacc, o);
        if (lane == 0) s_red[warp] = myacc;
        __syncthreads();
        if (tid == 0) {
            float t = 0.f;
            #pragma unroll
            for (int w = 0; w < 32; ++w) t += s_red[w];
            g_vsum[cta] = t;
        }
    } else {
        // ================= BACKWARD TEAM =================
        int id = cta - TEAM;
        int c0 = id * 32;
        int s0 = id >> 3;
        const CUtensorMap* mapB2 = &maps[1];
        if (tid == 0) asm volatile("prefetch.tensormap [%0];" :: "l"(mapB2));

        auto issue = [&](int idx) {
            int slot = idx % RING;
            uint32_t mb = mbar + slot * 8;
            mbar_expect(mb, SLOT_BYTES);
            int ff = 30 - idx / CPS, j = idx % CPS;
            int cc = s0 + j; if (cc >= CPS) cc -= CPS;
            tma3d(sbase + (uint32_t)slot * SLOT_BYTES, mapB2, c0, cc * CW, ff, mb);
        };

        int issued = 0;
        if (tid == 0)
            for (int i = 0; i < DEPTH; ++i) issue(i);
        issued = DEPTH;

        if (tid < 32) {
            g_z[31 * N + c0 + tid] = 1.0f;
            __threadfence();
        }
        __syncthreads();
        if (tid == 0) *(volatile int*)&g_flagB[31 * TEAM + id] = 1;

        for (int f = FF - 2; f >= 0; --f) {
            float p = 0.f;
            int g0 = (30 - f) * CPS;
            #pragma unroll
            for (int j = 0; j < CPS; ++j) {
                int idx = g0 + j;
                int cc = s0 + j; if (cc >= CPS) cc -= CPS;
                if (warp == 0) {
                    waitseg(g_flagB + (f + 1) * TEAM + cc * 8);
                    #pragma unroll
                    for (int t = 0; t < 8; ++t) {
                        int n = cc * CW + lane + t * 32;
                        s_v[n] = g_keep[(f + 1) * N + n] * g_z[(f + 1) * N + n];
                    }
                    if (lane == 0) mbar_wait(mbar + (idx % RING) * 8, (idx / RING) & 1);
                }
                __syncthreads();
                if (tid == 0 && issued < TOTAL) issue(issued);
                issued++;

                const float* sw = s_slot + (idx % RING) * SLOT_FLOATS;
                const float* vv = s_v + cc * CW;
                #pragma unroll
                for (int jj = 0; jj < 8; ++jj) { // row r = warp + 32*jj within chunk
                    int r = warp + jj * 32;
                    p += sw[r * 32 + lane] * vv[r];
                }
            }
            __syncthreads();                     // consumption done; s_red reuse safe
            s_red[lane * 33 + warp] = p;         // padded transpose
            __syncthreads();
            float q = s_red[warp * 33 + lane];   // warp w reduces col c0+w
            #pragma unroll
            for (int o = 16; o; o >>= 1)
                q += __shfl_xor_sync(0xffffffffu, q, o);
            if (lane == 0) {
                g_z[f * N + c0 + warp] = 1.0f + q;
                __threadfence();
            }
            __syncthreads();
            if (tid == 0) *(volatile int*)&g_flagB[f * TEAM + id] = 1;
        }
    }

    // ================= FUSED FINAL =================
    __threadfence();
    __syncthreads();
    if (tid == 0) atomicAdd(&g_cntAll, 1);
    if (cta == 0) {
        if (tid == 0) {
            volatile int* c = &g_cntAll;
            while (*c < NCTA) { }
            __threadfence();
        }
        __syncthreads();
        float t = (tid < TEAM) ? g_vsum[tid] : 0.f;
        if (tid < 128) {
            #pragma unroll
            for (int o = 16; o; o >>= 1) t += __shfl_xor_sync(0xffffffffu, t, o);
            if ((tid & 31) == 0) s_red[tid >> 5] = t;
        }
        __syncthreads();
        if (tid == 0) s_red[0] = s_red[0] + s_red[1] + s_red[2] + s_red[3];
        __syncthreads();
        float TOT = s_red[0];
        int cf = cand[3 * tid];
        int cn = cand[3 * tid + 1] * 64 + cand[3 * tid + 2];
        out[tid] = TOT - g_v[cf * N + cn] * g_z[cf * N + cn];
    }
}

// ---- host ----
typedef CUresult (*EncodeFn)(CUtensorMap*, CUtensorMapDataType, cuuint32_t, void*,
                             const cuuint64_t*, const cuuint64_t*, const cuuint32_t*,
                             const cuuint32_t*, CUtensorMapInterleave, CUtensorMapSwizzle,
                             CUtensorMapL2promotion, CUtensorMapFloatOOBfill);

extern "C" void kernel_launch(void* const* d_in, const int* in_sizes, int n_in,
                              void* d_out, int out_size) {
    const float* weights = (const float*)d_in[0];
    const float* biases  = (const float*)d_in[1];
    const int*   sel     = (const int*)d_in[2];
    const int*   cand    = (const int*)d_in[3];
    float*       out     = (float*)d_out;

    static EncodeFn enc = nullptr;
    if (!enc) {
        void* p = nullptr;
        cudaDriverEntryPointQueryResult st;
        cudaGetDriverEntryPoint("cuTensorMapEncodeTiled", &p, cudaEnableDefault, &st);
        enc = (EncodeFn)p;
    }

    static CUtensorMap h_maps[2];
    cuuint64_t dims[3] = {N, N, FF - 1};
    cuuint64_t strides[2] = {(cuuint64_t)N * 4, (cuuint64_t)N * N * 4};
    cuuint32_t es[3] = {1, 1, 1};
    cuuint32_t boxF[3] = {64, 32, 1};    // fwd: 256B inner x 32 rows (4 sub-boxes/chunk)
    cuuint32_t boxB[3] = {32, 256, 1};   // bwd: 128B inner x 256 rows (1 box/chunk)
    enc(&h_maps[0], CU_TENSOR_MAP_DATA_TYPE_FLOAT32, 3, (void*)weights, dims, strides,
        boxF, es, CU_TENSOR_MAP_INTERLEAVE_NONE, CU_TENSOR_MAP_SWIZZLE_NONE,
        CU_TENSOR_MAP_L2_PROMOTION_L2_128B, CU_TENSOR_MAP_FLOAT_OOB_FILL_NONE);
    enc(&h_maps[1], CU_TENSOR_MAP_DATA_TYPE_FLOAT32, 3, (void*)weights, dims, strides,
        boxB, es, CU_TENSOR_MAP_INTERLEAVE_NONE, CU_TENSOR_MAP_SWIZZLE_NONE,
        CU_TENSOR_MAP_L2_PROMOTION_L2_128B, CU_TENSOR_MAP_FLOAT_OOB_FILL_NONE);
    cudaMemcpyToSymbolAsync(g_tmaps, h_maps, sizeof(h_maps), 0, cudaMemcpyHostToDevice, 0);

    void* mapsym = nullptr;
    cudaGetSymbolAddress(&mapsym, g_tmaps);
    const CUtensorMap* dmaps = (const CUtensorMap*)mapsym;

    cudaFuncSetAttribute(solve_kernel, cudaFuncAttributeMaxDynamicSharedMemorySize, SMEM_BYTES);

    setup_kernel<<<1, NTHR>>>(sel);
    solve_kernel<<<NCTA, NTHR, SMEM_BYTES>>>(dmaps, biases, cand, out);
}